// round 16
// baseline (speedup 1.0000x reference)
#include <cuda_runtime.h>
#include <cfloat>
#include <math.h>

// Problem constants
#define NN 16384
#define MM 32768
#define KK 8
#define CC 256
#define TILE 2048             // cond candidates per shared tile
#define NTILES (MM / TILE)    // 16

// Scratch (device globals; no allocations allowed)
__device__ __align__(16) float g_cx[MM];   // -2 * transformed cond x
__device__ __align__(16) float g_cy[MM];   // -2 * transformed cond y
__device__ __align__(16) float g_cz[MM];   // -2 * transformed cond z
__device__ __align__(16) float g_c2[MM];   // |c|^2 (XLA fmla chain)
__device__ float g_favg[NN * CC];      // weighted-average features
__device__ float g_h1[NN * CC];        // MLP intermediate 1
__device__ float g_h2[NN * CC];        // MLP intermediate 2
__device__ float g_tf[CC];             // timestep feature vector

// ---------------------------------------------------------------------------
// Kernel 0: pre-transform cond coords: (-2cx,-2cy,-2cz, |c|^2), SoA.
// cx recoverable bit-exactly as -0.5 * (-2cx)  (x2 / x0.5 are exact in fp).
// ---------------------------------------------------------------------------
__global__ void k_prep(const int* __restrict__ cond_c) {
    int i = blockIdx.x * 256 + threadIdx.x;
    int4 cc = ((const int4*)cond_c)[i];
    float cx = __fmul_rn(__fadd_rn((float)cc.y, 0.5f), 0.01f);
    float cy = __fmul_rn(__fadd_rn((float)cc.z, 0.5f), 0.01f);
    float cz = __fmul_rn(__fadd_rn((float)cc.w, 0.5f), 0.01f);
    g_cx[i] = -2.0f * cx;
    g_cy[i] = -2.0f * cy;
    g_cz[i] = -2.0f * cz;
    g_c2[i] = __fmaf_rn(cz, cz, __fmaf_rn(cy, cy, __fmul_rn(cx, cx)));
}

// ---------------------------------------------------------------------------
// Kernel 1: timestep embedding -> 2-layer MLP -> g_tf[256]
// ---------------------------------------------------------------------------
__global__ void k_tfeats(const float* __restrict__ t,
                         const float* __restrict__ Wt1, const float* __restrict__ bt1,
                         const float* __restrict__ Wt2, const float* __restrict__ bt2) {
    __shared__ float emb[96];
    __shared__ float h1[96];
    int tid = threadIdx.x;
    float tv = t[0];
    if (tid < 48) {
        const double c64 = -9.210340371976184 / 47.0;
        float cf = (float)c64;
        float arg = __fmul_rn((float)tid, cf);
        float f = (float)exp((double)arg);
        float e = __fmul_rn(tv, f);
        emb[tid]      = (float)sin((double)e);
        emb[tid + 48] = (float)cos((double)e);
    }
    __syncthreads();
    if (tid < 96) {
        float acc = 0.0f;
        #pragma unroll 8
        for (int j = 0; j < 96; ++j) acc += emb[j] * Wt1[tid * 96 + j];
        acc += bt1[tid];
        h1[tid] = (acc >= 0.0f) ? acc : 0.1f * acc;
    }
    __syncthreads();
    if (tid < 256) {
        float acc = 0.0f;
        #pragma unroll 8
        for (int j = 0; j < 96; ++j) acc += h1[j] * Wt2[tid * 96 + j];
        acc += bt2[tid];
        g_tf[tid] = acc;
    }
}

// ---------------------------------------------------------------------------
// Packed f32x2 helpers (two independent IEEE-RN fp32 lanes)
// ---------------------------------------------------------------------------
__device__ __forceinline__ unsigned long long pack2(float x) {
    unsigned long long r;
    asm("mov.b64 %0, {%1, %1};" : "=l"(r) : "f"(x));
    return r;
}

__device__ __forceinline__ void ffma2(unsigned long long& acc,
                                      unsigned long long a, unsigned long long b) {
    asm("fma.rn.f32x2 %0, %1, %2, %0;" : "+l"(acc) : "l"(a), "l"(b));
}

__device__ __forceinline__ void unpack2(unsigned long long v, float& lo, float& hi) {
    asm("mov.b64 {%0, %1}, %2;" : "=f"(lo), "=f"(hi) : "l"(v));
}

// Filter: s_lane = px*X + py*Y + pz*Z + C2  (3 packed fma) ~= d - |n|^2
__device__ __forceinline__ void dot3p(unsigned long long px, unsigned long long py,
                                      unsigned long long pz,
                                      unsigned long long X, unsigned long long Y,
                                      unsigned long long Z, unsigned long long C2,
                                      float& s0, float& s1) {
    asm("{\n\t"
        ".reg .b64 t;\n\t"
        "fma.rn.f32x2 t, %4, %7, %8;\n\t"
        "fma.rn.f32x2 t, %3, %6, t;\n\t"
        "fma.rn.f32x2 t, %2, %5, t;\n\t"
        "mov.b64 {%0, %1}, t;\n\t"
        "}"
        : "=f"(s0), "=f"(s1)
        : "l"(px), "l"(py), "l"(pz), "l"(X), "l"(Y), "l"(Z), "l"(C2));
}

// Exact reference distance from stored (-2c) values: cx = -0.5*X bit-exact,
// dx = add(nx, 0.5*X) = fl(nx - cx); XLA fmla chain.
__device__ __forceinline__ float exactd(float nx, float ny, float nz,
                                        float X, float Y, float Z) {
    float dx = __fadd_rn(nx, 0.5f * X);
    float dy = __fadd_rn(ny, 0.5f * Y);
    float dz = __fadd_rn(nz, 0.5f * Z);
    return __fmaf_rn(dz, dz, __fmaf_rn(dy, dy, __fmul_rn(dx, dx)));
}

// Sorted insert, strict '<' (ties keep earlier=lower-index entry) — matches
// the reference top_k semantics when candidates arrive in ascending index.
__device__ __forceinline__ void insert8(float d, int idx, float* bd, int* bi) {
    if (d < bd[KK - 1]) {
        bd[KK - 1] = d;
        bi[KK - 1] = idx;
        #pragma unroll
        for (int q = KK - 1; q > 0; --q) {
            if (bd[q] < bd[q - 1]) {
                float td = bd[q]; bd[q] = bd[q - 1]; bd[q - 1] = td;
                int   ti = bi[q]; bi[q] = bi[q - 1]; bi[q - 1] = ti;
            }
        }
    }
}

union F4U {
    float4 v;
    unsigned long long u[2];
};

// ---------------------------------------------------------------------------
// Kernel 2: warp-cooperative KNN + weights + feature gather, fused.
// One warp processes 2 nodes over ALL 32768 candidates. Fast path uses the
// 3-packed-op dot filter s ~= d - |n|^2 vs thr_s = (thr - n^2) + margin;
// margin (0.008 + 4e-6 n^2) provably dominates all fp error -> no false
// negatives. Windows shfl the packed candidate data, recompute the EXACT
// XLA fmla distance, and insert ascending-index with strict '<' -> selection
// and tie semantics bit-identical to the reference.
// ---------------------------------------------------------------------------
__global__ void __launch_bounds__(256) k_knn(const int* __restrict__ node_c,
                                             const float* __restrict__ cond_feats) {
    __shared__ __align__(16) float sx[TILE];
    __shared__ __align__(16) float sy[TILE];
    __shared__ __align__(16) float sz[TILE];
    __shared__ __align__(16) float sc[TILE];

    const int tid  = threadIdx.x;
    const int warp = tid >> 5;
    const int lane = tid & 31;
    const int nbase = blockIdx.x * 16 + warp * 2;   // 8 warps x 2 nodes
    const unsigned FULL = 0xffffffffu;

    float nxs[2], nys[2], nzs[2], n2[2], marg[2];
    unsigned long long px[2], py[2], pz[2];
    #pragma unroll
    for (int u = 0; u < 2; ++u) {
        int4 nc = ((const int4*)node_c)[nbase + u];
        nxs[u] = __fmul_rn(__fadd_rn((float)nc.y, 8.0f), 0.05f);
        nys[u] = __fmul_rn(__fadd_rn((float)nc.z, 8.0f), 0.05f);
        nzs[u] = __fmul_rn(__fadd_rn((float)nc.w, 8.0f), 0.05f);
        px[u] = pack2(nxs[u]);
        py[u] = pack2(nys[u]);
        pz[u] = pack2(nzs[u]);
        n2[u] = __fmaf_rn(nzs[u], nzs[u], __fmaf_rn(nys[u], nys[u],
                          __fmul_rn(nxs[u], nxs[u])));
        marg[u] = 0.008f + 4e-6f * n2[u];
    }

    float bd0[KK], bd1[KK];
    int   bi0[KK], bi1[KK];
    #pragma unroll
    for (int s = 0; s < KK; ++s) {
        bd0[s] = FLT_MAX; bi0[s] = 0x7fffffff;
        bd1[s] = FLT_MAX; bi1[s] = 0x7fffffff;
    }
    float thrs0 = FLT_MAX, thrs1 = FLT_MAX;   // filter thresholds (s-domain)

    for (int tile = 0; tile < NTILES; ++tile) {
        __syncthreads();
        {
            const float4* gx = (const float4*)g_cx + tile * (TILE / 4);
            const float4* gy = (const float4*)g_cy + tile * (TILE / 4);
            const float4* gz = (const float4*)g_cz + tile * (TILE / 4);
            const float4* gc = (const float4*)g_c2 + tile * (TILE / 4);
            #pragma unroll
            for (int i = 0; i < TILE / 4 / 256 * 256; i += 256) {
                ((float4*)sx)[i + tid] = gx[i + tid];
                ((float4*)sy)[i + tid] = gy[i + tid];
                ((float4*)sz)[i + tid] = gz[i + tid];
                ((float4*)sc)[i + tid] = gc[i + tid];
            }
        }
        __syncthreads();

        #pragma unroll 1
        for (int step = 0; step < TILE / 128; ++step) {
            const int jb = step * 128 + lane * 4;
            F4U X, Y, Z, C;
            X.v = *(const float4*)&sx[jb];
            Y.v = *(const float4*)&sy[jb];
            Z.v = *(const float4*)&sz[jb];
            C.v = *(const float4*)&sc[jb];
            const int gbase = tile * TILE + step * 128;

            // ---- node 0 ----
            {
                float s0, s1, s2, s3;
                dot3p(px[0], py[0], pz[0], X.u[0], Y.u[0], Z.u[0], C.u[0], s0, s1);
                dot3p(px[0], py[0], pz[0], X.u[1], Y.u[1], Z.u[1], C.u[1], s2, s3);
                float mn = fminf(fminf(s0, s1), fminf(s2, s3));
                unsigned mask = __ballot_sync(FULL, mn <= thrs0);
                while (mask) {
                    int b = __ffs(mask) - 1; mask &= mask - 1;
                    unsigned long long xu0 = __shfl_sync(FULL, X.u[0], b);
                    unsigned long long xu1 = __shfl_sync(FULL, X.u[1], b);
                    unsigned long long yu0 = __shfl_sync(FULL, Y.u[0], b);
                    unsigned long long yu1 = __shfl_sync(FULL, Y.u[1], b);
                    unsigned long long zu0 = __shfl_sync(FULL, Z.u[0], b);
                    unsigned long long zu1 = __shfl_sync(FULL, Z.u[1], b);
                    float x0, x1, x2, x3, y0, y1, y2, y3, z0, z1, z2, z3;
                    unpack2(xu0, x0, x1); unpack2(xu1, x2, x3);
                    unpack2(yu0, y0, y1); unpack2(yu1, y2, y3);
                    unpack2(zu0, z0, z1); unpack2(zu1, z2, z3);
                    int gi = gbase + b * 4;
                    insert8(exactd(nxs[0], nys[0], nzs[0], x0, y0, z0), gi,     bd0, bi0);
                    insert8(exactd(nxs[0], nys[0], nzs[0], x1, y1, z1), gi + 1, bd0, bi0);
                    insert8(exactd(nxs[0], nys[0], nzs[0], x2, y2, z2), gi + 2, bd0, bi0);
                    insert8(exactd(nxs[0], nys[0], nzs[0], x3, y3, z3), gi + 3, bd0, bi0);
                    thrs0 = __fadd_rn(__fadd_rn(bd0[KK - 1], -n2[0]), marg[0]);
                }
            }
            // ---- node 1 ----
            {
                float s0, s1, s2, s3;
                dot3p(px[1], py[1], pz[1], X.u[0], Y.u[0], Z.u[0], C.u[0], s0, s1);
                dot3p(px[1], py[1], pz[1], X.u[1], Y.u[1], Z.u[1], C.u[1], s2, s3);
                float mn = fminf(fminf(s0, s1), fminf(s2, s3));
                unsigned mask = __ballot_sync(FULL, mn <= thrs1);
                while (mask) {
                    int b = __ffs(mask) - 1; mask &= mask - 1;
                    unsigned long long xu0 = __shfl_sync(FULL, X.u[0], b);
                    unsigned long long xu1 = __shfl_sync(FULL, X.u[1], b);
                    unsigned long long yu0 = __shfl_sync(FULL, Y.u[0], b);
                    unsigned long long yu1 = __shfl_sync(FULL, Y.u[1], b);
                    unsigned long long zu0 = __shfl_sync(FULL, Z.u[0], b);
                    unsigned long long zu1 = __shfl_sync(FULL, Z.u[1], b);
                    float x0, x1, x2, x3, y0, y1, y2, y3, z0, z1, z2, z3;
                    unpack2(xu0, x0, x1); unpack2(xu1, x2, x3);
                    unpack2(yu0, y0, y1); unpack2(yu1, y2, y3);
                    unpack2(zu0, z0, z1); unpack2(zu1, z2, z3);
                    int gi = gbase + b * 4;
                    insert8(exactd(nxs[1], nys[1], nzs[1], x0, y0, z0), gi,     bd1, bi1);
                    insert8(exactd(nxs[1], nys[1], nzs[1], x1, y1, z1), gi + 1, bd1, bi1);
                    insert8(exactd(nxs[1], nys[1], nzs[1], x2, y2, z2), gi + 2, bd1, bi1);
                    insert8(exactd(nxs[1], nys[1], nzs[1], x3, y3, z3), gi + 3, bd1, bi1);
                    thrs1 = __fadd_rn(__fadd_rn(bd1[KK - 1], -n2[1]), marg[1]);
                }
            }
        }
    }

    #pragma unroll
    for (int u = 0; u < 2; ++u) {
        const float* bd = (u == 0) ? bd0 : bd1;
        const int*   bi = (u == 0) ? bi0 : bi1;

        float w[KK];
        float wsum = 0.0f;
        #pragma unroll
        for (int k = 0; k < KK; ++k) {
            float dist = fmaxf(sqrtf(bd[k]), 1e-6f);
            w[k] = 1.0f / dist;
            wsum += w[k];
        }
        #pragma unroll
        for (int k = 0; k < KK; ++k) w[k] = w[k] / wsum;

        const float* rp[KK];
        #pragma unroll
        for (int k = 0; k < KK; ++k) rp[k] = cond_feats + (size_t)bi[k] * CC;

        float* outp = g_favg + (size_t)(nbase + u) * CC;
        #pragma unroll
        for (int j = 0; j < 8; ++j) {
            int c = lane + j * 32;
            float acc = 0.0f;
            #pragma unroll
            for (int k = 0; k < KK; ++k) acc = fmaf(w[k], rp[k][c], acc);
            outp[c] = acc;
        }
    }
}

// ---------------------------------------------------------------------------
// Kernel 4: packed-f32x2 SGEMM  Y[16384,256] = X @ W^T (+bias, act, tf)
// (proven 60.5us variant, unchanged)
// ---------------------------------------------------------------------------
#define SP 132   // smem pitch (floats)
template<int ACT, int ADDTF>
__global__ void __launch_bounds__(256, 2) k_gemm(const float* __restrict__ X,
                                                 const float* __restrict__ W,
                                                 const float* __restrict__ bias,
                                                 float* __restrict__ Y) {
    __shared__ float As[2][8][SP];
    __shared__ float Bs[2][8][SP];

    const int t   = threadIdx.x;
    const int tx  = t & 15;
    const int ty  = t >> 4;
    const int row0 = blockIdx.x * 128;
    const int col0 = blockIdx.y * 128;

    const int lrow = t >> 1;
    const int lk4  = (t & 1) * 4;
    const float* Ag = X + (size_t)(row0 + lrow) * CC + lk4;
    const float* Bg = W + (size_t)(col0 + lrow) * CC + lk4;

    float4 afrag = *(const float4*)Ag;
    float4 bfrag = *(const float4*)Bg;

    As[0][lk4 + 0][lrow] = afrag.x;
    As[0][lk4 + 1][lrow] = afrag.y;
    As[0][lk4 + 2][lrow] = afrag.z;
    As[0][lk4 + 3][lrow] = afrag.w;
    Bs[0][lk4 + 0][lrow] = bfrag.x;
    Bs[0][lk4 + 1][lrow] = bfrag.y;
    Bs[0][lk4 + 2][lrow] = bfrag.z;
    Bs[0][lk4 + 3][lrow] = bfrag.w;
    __syncthreads();

    unsigned long long acc2[4][8];
    #pragma unroll
    for (int i = 0; i < 4; ++i)
        #pragma unroll
        for (int j = 0; j < 8; ++j) acc2[i][j] = 0ull;

    #pragma unroll 1
    for (int kt = 0; kt < 32; ++kt) {
        int buf = kt & 1;
        if (kt < 31) {
            afrag = *(const float4*)(Ag + (kt + 1) * 8);
            bfrag = *(const float4*)(Bg + (kt + 1) * 8);
        }

        #pragma unroll
        for (int kk = 0; kk < 8; ++kk) {
            F4U a0, a1, b0, b1;
            a0.v = *(const float4*)&As[buf][kk][ty * 8];
            a1.v = *(const float4*)&As[buf][kk][ty * 8 + 4];
            b0.v = *(const float4*)&Bs[buf][kk][tx * 8];
            b1.v = *(const float4*)&Bs[buf][kk][tx * 8 + 4];

            unsigned long long ap[4] = {a0.u[0], a0.u[1], a1.u[0], a1.u[1]};
            unsigned long long bp[8];
            bp[0] = pack2(b0.v.x); bp[1] = pack2(b0.v.y);
            bp[2] = pack2(b0.v.z); bp[3] = pack2(b0.v.w);
            bp[4] = pack2(b1.v.x); bp[5] = pack2(b1.v.y);
            bp[6] = pack2(b1.v.z); bp[7] = pack2(b1.v.w);

            #pragma unroll
            for (int i = 0; i < 4; ++i)
                #pragma unroll
                for (int j = 0; j < 8; ++j)
                    ffma2(acc2[i][j], ap[i], bp[j]);
        }

        if (kt < 31) {
            int nb = buf ^ 1;
            As[nb][lk4 + 0][lrow] = afrag.x;
            As[nb][lk4 + 1][lrow] = afrag.y;
            As[nb][lk4 + 2][lrow] = afrag.z;
            As[nb][lk4 + 3][lrow] = afrag.w;
            Bs[nb][lk4 + 0][lrow] = bfrag.x;
            Bs[nb][lk4 + 1][lrow] = bfrag.y;
            Bs[nb][lk4 + 2][lrow] = bfrag.z;
            Bs[nb][lk4 + 3][lrow] = bfrag.w;
            __syncthreads();
        }
    }

    float bb[8], tf[8];
    #pragma unroll
    for (int j = 0; j < 8; ++j) {
        int c = col0 + tx * 8 + j;
        bb[j] = bias[c];
        if (ADDTF) tf[j] = g_tf[c];
    }

    #pragma unroll
    for (int i2 = 0; i2 < 4; ++i2) {
        float oL[8], oH[8];
        #pragma unroll
        for (int j = 0; j < 8; ++j) {
            float lo, hi;
            unpack2(acc2[i2][j], lo, hi);
            float vL = lo + bb[j];
            float vH = hi + bb[j];
            if (ACT) {
                vL = (vL >= 0.0f) ? vL : 0.1f * vL;
                vH = (vH >= 0.0f) ? vH : 0.1f * vH;
            }
            if (ADDTF) { vL += tf[j]; vH += tf[j]; }
            oL[j] = vL; oH[j] = vH;
        }
        int rL = row0 + ty * 8 + 2 * i2;
        float4* ypL = (float4*)(Y + (size_t)rL * CC + col0 + tx * 8);
        ypL[0] = make_float4(oL[0], oL[1], oL[2], oL[3]);
        ypL[1] = make_float4(oL[4], oL[5], oL[6], oL[7]);
        float4* ypH = (float4*)(Y + (size_t)(rL + 1) * CC + col0 + tx * 8);
        ypH[0] = make_float4(oH[0], oH[1], oH[2], oH[3]);
        ypH[1] = make_float4(oH[4], oH[5], oH[6], oH[7]);
    }
}

// ---------------------------------------------------------------------------
extern "C" void kernel_launch(void* const* d_in, const int* in_sizes, int n_in,
                              void* d_out, int out_size) {
    const int*   node_c     = (const int*)d_in[0];
    const int*   cond_c     = (const int*)d_in[1];
    const float* cond_feats = (const float*)d_in[2];
    const float* t          = (const float*)d_in[3];
    const float* W_proj     = (const float*)d_in[4];
    const float* b_proj     = (const float*)d_in[5];
    const float* W_l1       = (const float*)d_in[6];
    const float* b_l1       = (const float*)d_in[7];
    const float* W_l2       = (const float*)d_in[8];
    const float* b_l2       = (const float*)d_in[9];
    const float* W_t1       = (const float*)d_in[10];
    const float* b_t1       = (const float*)d_in[11];
    const float* W_t2       = (const float*)d_in[12];
    const float* b_t2       = (const float*)d_in[13];
    float* out = (float*)d_out;

    float* h1; cudaGetSymbolAddress((void**)&h1, g_h1);
    float* h2; cudaGetSymbolAddress((void**)&h2, g_h2);
    float* fa; cudaGetSymbolAddress((void**)&fa, g_favg);

    k_prep<<<MM / 256, 256>>>(cond_c);
    k_tfeats<<<1, 256>>>(t, W_t1, b_t1, W_t2, b_t2);

    k_knn<<<NN / 16, 256>>>(node_c, cond_feats);   // 1024 blocks, 8 warps x 2 nodes

    dim3 gg(NN / 128, CC / 128);   // 128 x 2 = 256 blocks
    k_gemm<0, 0><<<gg, 256>>>(fa, W_proj, b_proj, h1);
    k_gemm<1, 0><<<gg, 256>>>(h1, W_l1, b_l1, h2);
    k_gemm<0, 1><<<gg, 256>>>(h2, W_l2, b_l2, out);

    (void)in_sizes; (void)n_in; (void)out_size;
}

// round 17
// speedup vs baseline: 1.4108x; 1.4108x over previous
#include <cuda_runtime.h>
#include <cfloat>
#include <math.h>

// Problem constants
#define NN 16384
#define MM 32768
#define KK 8
#define CC 256
#define TILE 2048             // cond candidates per shared tile
#define NTILES (MM / TILE)    // 16

// Scratch (device globals; no allocations allowed)
__device__ __align__(16) float g_cx[MM];   // negated transformed cond x
__device__ __align__(16) float g_cy[MM];
__device__ __align__(16) float g_cz[MM];
__device__ float g_favg[NN * CC];      // weighted-average features
__device__ float g_h1[NN * CC];        // MLP intermediate 1
__device__ float g_h2[NN * CC];        // MLP intermediate 2
__device__ float g_tf[CC];             // timestep feature vector

// ---------------------------------------------------------------------------
// Kernel 0: pre-transform cond coords (negated, SoA)
// ---------------------------------------------------------------------------
__global__ void k_prep(const int* __restrict__ cond_c) {
    int i = blockIdx.x * 256 + threadIdx.x;
    int4 cc = ((const int4*)cond_c)[i];
    g_cx[i] = -__fmul_rn(__fadd_rn((float)cc.y, 0.5f), 0.01f);
    g_cy[i] = -__fmul_rn(__fadd_rn((float)cc.z, 0.5f), 0.01f);
    g_cz[i] = -__fmul_rn(__fadd_rn((float)cc.w, 0.5f), 0.01f);
}

// ---------------------------------------------------------------------------
// Kernel 1: timestep embedding -> 2-layer MLP -> g_tf[256]
// ---------------------------------------------------------------------------
__global__ void k_tfeats(const float* __restrict__ t,
                         const float* __restrict__ Wt1, const float* __restrict__ bt1,
                         const float* __restrict__ Wt2, const float* __restrict__ bt2) {
    __shared__ float emb[96];
    __shared__ float h1[96];
    int tid = threadIdx.x;
    float tv = t[0];
    if (tid < 48) {
        const double c64 = -9.210340371976184 / 47.0;
        float cf = (float)c64;
        float arg = __fmul_rn((float)tid, cf);
        float f = (float)exp((double)arg);
        float e = __fmul_rn(tv, f);
        emb[tid]      = (float)sin((double)e);
        emb[tid + 48] = (float)cos((double)e);
    }
    __syncthreads();
    if (tid < 96) {
        float acc = 0.0f;
        #pragma unroll 8
        for (int j = 0; j < 96; ++j) acc += emb[j] * Wt1[tid * 96 + j];
        acc += bt1[tid];
        h1[tid] = (acc >= 0.0f) ? acc : 0.1f * acc;
    }
    __syncthreads();
    if (tid < 256) {
        float acc = 0.0f;
        #pragma unroll 8
        for (int j = 0; j < 96; ++j) acc += h1[j] * Wt2[tid * 96 + j];
        acc += bt2[tid];
        g_tf[tid] = acc;
    }
}

// ---------------------------------------------------------------------------
// Packed f32x2 helpers (two independent IEEE-RN fp32 lanes -> bit-exact)
// ---------------------------------------------------------------------------
__device__ __forceinline__ unsigned long long pack2(float x) {
    unsigned long long r;
    asm("mov.b64 %0, {%1, %1};" : "=l"(r) : "f"(x));
    return r;
}

__device__ __forceinline__ void ffma2(unsigned long long& acc,
                                      unsigned long long a, unsigned long long b) {
    asm("fma.rn.f32x2 %0, %1, %2, %0;" : "+l"(acc) : "l"(a), "l"(b));
}

__device__ __forceinline__ void unpack2(unsigned long long v, float& lo, float& hi) {
    asm("mov.b64 {%0, %1}, %2;" : "=f"(lo), "=f"(hi) : "l"(v));
}

// d_lane = fma(dz,dz, fma(dy,dy, dx*dx)) with dx = nx + (-cx)  (XLA scheme)
__device__ __forceinline__ void dist2x2(unsigned long long nx, unsigned long long ny,
                                        unsigned long long nz,
                                        unsigned long long cx, unsigned long long cy,
                                        unsigned long long cz,
                                        float& d0, float& d1) {
    asm("{\n\t"
        ".reg .b64 dx, dy, dz, t;\n\t"
        "add.rn.f32x2 dx, %2, %5;\n\t"
        "add.rn.f32x2 dy, %3, %6;\n\t"
        "add.rn.f32x2 dz, %4, %7;\n\t"
        "mul.rn.f32x2 t, dx, dx;\n\t"
        "fma.rn.f32x2 t, dy, dy, t;\n\t"
        "fma.rn.f32x2 t, dz, dz, t;\n\t"
        "mov.b64 {%0, %1}, t;\n\t"
        "}"
        : "=f"(d0), "=f"(d1)
        : "l"(nx), "l"(ny), "l"(nz), "l"(cx), "l"(cy), "l"(cz));
}

// Sorted insert, strict '<' (ties keep earlier=lower-index entry) — matches
// the reference top_k semantics when candidates arrive in ascending index.
__device__ __forceinline__ void insert8(float d, int idx, float* bd, int* bi) {
    if (d < bd[KK - 1]) {
        bd[KK - 1] = d;
        bi[KK - 1] = idx;
        #pragma unroll
        for (int q = KK - 1; q > 0; --q) {
            if (bd[q] < bd[q - 1]) {
                float td = bd[q]; bd[q] = bd[q - 1]; bd[q - 1] = td;
                int   ti = bi[q]; bi[q] = bi[q - 1]; bi[q - 1] = ti;
            }
        }
    }
}

union F4U {
    float4 v;
    unsigned long long u[2];
};

// ---------------------------------------------------------------------------
// Kernel 2: warp-cooperative KNN + weights + feature gather, fused.
// One warp processes 2 nodes over ALL 32768 candidates. All 32 lanes share
// one node's selection state (replicated registers); __ballot guard skips
// most windows uniformly. Identical fp scheme + ascending-index strict-'<'
// insert -> selection and tie semantics bit-identical to reference.
// Changes vs proven 493.7 build: (a) thr update hoisted out of the window
// loop (semantically identical here — no in-window thr consumer), (b) step
// loop unroll 2 to overlap consecutive steps' independent chains.
// ---------------------------------------------------------------------------
__global__ void __launch_bounds__(256) k_knn(const int* __restrict__ node_c,
                                             const float* __restrict__ cond_feats) {
    __shared__ __align__(16) float sx[TILE];
    __shared__ __align__(16) float sy[TILE];
    __shared__ __align__(16) float sz[TILE];

    const int tid  = threadIdx.x;
    const int warp = tid >> 5;
    const int lane = tid & 31;
    const int nbase = blockIdx.x * 16 + warp * 2;   // 8 warps x 2 nodes
    const unsigned FULL = 0xffffffffu;

    unsigned long long nx[2], ny[2], nz[2];
    #pragma unroll
    for (int u = 0; u < 2; ++u) {
        int4 nc = ((const int4*)node_c)[nbase + u];
        nx[u] = pack2(__fmul_rn(__fadd_rn((float)nc.y, 8.0f), 0.05f));
        ny[u] = pack2(__fmul_rn(__fadd_rn((float)nc.z, 8.0f), 0.05f));
        nz[u] = pack2(__fmul_rn(__fadd_rn((float)nc.w, 8.0f), 0.05f));
    }

    float bd0[KK], bd1[KK];
    int   bi0[KK], bi1[KK];
    #pragma unroll
    for (int s = 0; s < KK; ++s) {
        bd0[s] = FLT_MAX; bi0[s] = 0x7fffffff;
        bd1[s] = FLT_MAX; bi1[s] = 0x7fffffff;
    }
    float thr0 = FLT_MAX, thr1 = FLT_MAX;

    for (int tile = 0; tile < NTILES; ++tile) {
        __syncthreads();
        {
            const float4* gx = (const float4*)g_cx + tile * (TILE / 4);
            const float4* gy = (const float4*)g_cy + tile * (TILE / 4);
            const float4* gz = (const float4*)g_cz + tile * (TILE / 4);
            #pragma unroll
            for (int i = 0; i < TILE / 4 / 256 * 256; i += 256) {
                ((float4*)sx)[i + tid] = gx[i + tid];
                ((float4*)sy)[i + tid] = gy[i + tid];
                ((float4*)sz)[i + tid] = gz[i + tid];
            }
        }
        __syncthreads();

        #pragma unroll 2
        for (int step = 0; step < TILE / 128; ++step) {
            const int jb = step * 128 + lane * 4;
            F4U X, Y, Z;
            X.v = *(const float4*)&sx[jb];
            Y.v = *(const float4*)&sy[jb];
            Z.v = *(const float4*)&sz[jb];
            const int gbase = tile * TILE + step * 128;

            // ---- node 0 ----
            {
                float d0, d1, d2, d3;
                dist2x2(nx[0], ny[0], nz[0], X.u[0], Y.u[0], Z.u[0], d0, d1);
                dist2x2(nx[0], ny[0], nz[0], X.u[1], Y.u[1], Z.u[1], d2, d3);
                float mn = fminf(fminf(d0, d1), fminf(d2, d3));
                unsigned mask = __ballot_sync(FULL, mn < thr0);
                if (mask) {
                    do {
                        int b = __ffs(mask) - 1; mask &= mask - 1;
                        float e0 = __shfl_sync(FULL, d0, b);
                        float e1 = __shfl_sync(FULL, d1, b);
                        float e2 = __shfl_sync(FULL, d2, b);
                        float e3 = __shfl_sync(FULL, d3, b);
                        int gi = gbase + b * 4;
                        insert8(e0, gi,     bd0, bi0);
                        insert8(e1, gi + 1, bd0, bi0);
                        insert8(e2, gi + 2, bd0, bi0);
                        insert8(e3, gi + 3, bd0, bi0);
                    } while (mask);
                    thr0 = bd0[KK - 1];
                }
            }
            // ---- node 1 ----
            {
                float d0, d1, d2, d3;
                dist2x2(nx[1], ny[1], nz[1], X.u[0], Y.u[0], Z.u[0], d0, d1);
                dist2x2(nx[1], ny[1], nz[1], X.u[1], Y.u[1], Z.u[1], d2, d3);
                float mn = fminf(fminf(d0, d1), fminf(d2, d3));
                unsigned mask = __ballot_sync(FULL, mn < thr1);
                if (mask) {
                    do {
                        int b = __ffs(mask) - 1; mask &= mask - 1;
                        float e0 = __shfl_sync(FULL, d0, b);
                        float e1 = __shfl_sync(FULL, d1, b);
                        float e2 = __shfl_sync(FULL, d2, b);
                        float e3 = __shfl_sync(FULL, d3, b);
                        int gi = gbase + b * 4;
                        insert8(e0, gi,     bd1, bi1);
                        insert8(e1, gi + 1, bd1, bi1);
                        insert8(e2, gi + 2, bd1, bi1);
                        insert8(e3, gi + 3, bd1, bi1);
                    } while (mask);
                    thr1 = bd1[KK - 1];
                }
            }
        }
    }

    #pragma unroll
    for (int u = 0; u < 2; ++u) {
        const float* bd = (u == 0) ? bd0 : bd1;
        const int*   bi = (u == 0) ? bi0 : bi1;

        float w[KK];
        float wsum = 0.0f;
        #pragma unroll
        for (int k = 0; k < KK; ++k) {
            float dist = fmaxf(sqrtf(bd[k]), 1e-6f);
            w[k] = 1.0f / dist;
            wsum += w[k];
        }
        #pragma unroll
        for (int k = 0; k < KK; ++k) w[k] = w[k] / wsum;

        const float* rp[KK];
        #pragma unroll
        for (int k = 0; k < KK; ++k) rp[k] = cond_feats + (size_t)bi[k] * CC;

        float* outp = g_favg + (size_t)(nbase + u) * CC;
        #pragma unroll
        for (int j = 0; j < 8; ++j) {
            int c = lane + j * 32;
            float acc = 0.0f;
            #pragma unroll
            for (int k = 0; k < KK; ++k) acc = fmaf(w[k], rp[k][c], acc);
            outp[c] = acc;
        }
    }
}

// ---------------------------------------------------------------------------
// Kernel 4: packed-f32x2 SGEMM  Y[16384,256] = X @ W^T (+bias, act, tf)
// (proven 60.5us variant, unchanged)
// ---------------------------------------------------------------------------
#define SP 132   // smem pitch (floats)
template<int ACT, int ADDTF>
__global__ void __launch_bounds__(256, 2) k_gemm(const float* __restrict__ X,
                                                 const float* __restrict__ W,
                                                 const float* __restrict__ bias,
                                                 float* __restrict__ Y) {
    __shared__ float As[2][8][SP];
    __shared__ float Bs[2][8][SP];

    const int t   = threadIdx.x;
    const int tx  = t & 15;
    const int ty  = t >> 4;
    const int row0 = blockIdx.x * 128;
    const int col0 = blockIdx.y * 128;

    const int lrow = t >> 1;
    const int lk4  = (t & 1) * 4;
    const float* Ag = X + (size_t)(row0 + lrow) * CC + lk4;
    const float* Bg = W + (size_t)(col0 + lrow) * CC + lk4;

    float4 afrag = *(const float4*)Ag;
    float4 bfrag = *(const float4*)Bg;

    As[0][lk4 + 0][lrow] = afrag.x;
    As[0][lk4 + 1][lrow] = afrag.y;
    As[0][lk4 + 2][lrow] = afrag.z;
    As[0][lk4 + 3][lrow] = afrag.w;
    Bs[0][lk4 + 0][lrow] = bfrag.x;
    Bs[0][lk4 + 1][lrow] = bfrag.y;
    Bs[0][lk4 + 2][lrow] = bfrag.z;
    Bs[0][lk4 + 3][lrow] = bfrag.w;
    __syncthreads();

    unsigned long long acc2[4][8];
    #pragma unroll
    for (int i = 0; i < 4; ++i)
        #pragma unroll
        for (int j = 0; j < 8; ++j) acc2[i][j] = 0ull;

    #pragma unroll 1
    for (int kt = 0; kt < 32; ++kt) {
        int buf = kt & 1;
        if (kt < 31) {
            afrag = *(const float4*)(Ag + (kt + 1) * 8);
            bfrag = *(const float4*)(Bg + (kt + 1) * 8);
        }

        #pragma unroll
        for (int kk = 0; kk < 8; ++kk) {
            F4U a0, a1, b0, b1;
            a0.v = *(const float4*)&As[buf][kk][ty * 8];
            a1.v = *(const float4*)&As[buf][kk][ty * 8 + 4];
            b0.v = *(const float4*)&Bs[buf][kk][tx * 8];
            b1.v = *(const float4*)&Bs[buf][kk][tx * 8 + 4];

            unsigned long long ap[4] = {a0.u[0], a0.u[1], a1.u[0], a1.u[1]};
            unsigned long long bp[8];
            bp[0] = pack2(b0.v.x); bp[1] = pack2(b0.v.y);
            bp[2] = pack2(b0.v.z); bp[3] = pack2(b0.v.w);
            bp[4] = pack2(b1.v.x); bp[5] = pack2(b1.v.y);
            bp[6] = pack2(b1.v.z); bp[7] = pack2(b1.v.w);

            #pragma unroll
            for (int i = 0; i < 4; ++i)
                #pragma unroll
                for (int j = 0; j < 8; ++j)
                    ffma2(acc2[i][j], ap[i], bp[j]);
        }

        if (kt < 31) {
            int nb = buf ^ 1;
            As[nb][lk4 + 0][lrow] = afrag.x;
            As[nb][lk4 + 1][lrow] = afrag.y;
            As[nb][lk4 + 2][lrow] = afrag.z;
            As[nb][lk4 + 3][lrow] = afrag.w;
            Bs[nb][lk4 + 0][lrow] = bfrag.x;
            Bs[nb][lk4 + 1][lrow] = bfrag.y;
            Bs[nb][lk4 + 2][lrow] = bfrag.z;
            Bs[nb][lk4 + 3][lrow] = bfrag.w;
            __syncthreads();
        }
    }

    float bb[8], tf[8];
    #pragma unroll
    for (int j = 0; j < 8; ++j) {
        int c = col0 + tx * 8 + j;
        bb[j] = bias[c];
        if (ADDTF) tf[j] = g_tf[c];
    }

    #pragma unroll
    for (int i2 = 0; i2 < 4; ++i2) {
        float oL[8], oH[8];
        #pragma unroll
        for (int j = 0; j < 8; ++j) {
            float lo, hi;
            unpack2(acc2[i2][j], lo, hi);
            float vL = lo + bb[j];
            float vH = hi + bb[j];
            if (ACT) {
                vL = (vL >= 0.0f) ? vL : 0.1f * vL;
                vH = (vH >= 0.0f) ? vH : 0.1f * vH;
            }
            if (ADDTF) { vL += tf[j]; vH += tf[j]; }
            oL[j] = vL; oH[j] = vH;
        }
        int rL = row0 + ty * 8 + 2 * i2;
        float4* ypL = (float4*)(Y + (size_t)rL * CC + col0 + tx * 8);
        ypL[0] = make_float4(oL[0], oL[1], oL[2], oL[3]);
        ypL[1] = make_float4(oL[4], oL[5], oL[6], oL[7]);
        float4* ypH = (float4*)(Y + (size_t)(rL + 1) * CC + col0 + tx * 8);
        ypH[0] = make_float4(oH[0], oH[1], oH[2], oH[3]);
        ypH[1] = make_float4(oH[4], oH[5], oH[6], oH[7]);
    }
}

// ---------------------------------------------------------------------------
extern "C" void kernel_launch(void* const* d_in, const int* in_sizes, int n_in,
                              void* d_out, int out_size) {
    const int*   node_c     = (const int*)d_in[0];
    const int*   cond_c     = (const int*)d_in[1];
    const float* cond_feats = (const float*)d_in[2];
    const float* t          = (const float*)d_in[3];
    const float* W_proj     = (const float*)d_in[4];
    const float* b_proj     = (const float*)d_in[5];
    const float* W_l1       = (const float*)d_in[6];
    const float* b_l1       = (const float*)d_in[7];
    const float* W_l2       = (const float*)d_in[8];
    const float* b_l2       = (const float*)d_in[9];
    const float* W_t1       = (const float*)d_in[10];
    const float* b_t1       = (const float*)d_in[11];
    const float* W_t2       = (const float*)d_in[12];
    const float* b_t2       = (const float*)d_in[13];
    float* out = (float*)d_out;

    float* h1; cudaGetSymbolAddress((void**)&h1, g_h1);
    float* h2; cudaGetSymbolAddress((void**)&h2, g_h2);
    float* fa; cudaGetSymbolAddress((void**)&fa, g_favg);

    k_prep<<<MM / 256, 256>>>(cond_c);
    k_tfeats<<<1, 256>>>(t, W_t1, b_t1, W_t2, b_t2);

    k_knn<<<NN / 16, 256>>>(node_c, cond_feats);   // 1024 blocks, 8 warps x 2 nodes

    dim3 gg(NN / 128, CC / 128);   // 128 x 2 = 256 blocks
    k_gemm<0, 0><<<gg, 256>>>(fa, W_proj, b_proj, h1);
    k_gemm<1, 0><<<gg, 256>>>(h1, W_l1, b_l1, h2);
    k_gemm<0, 1><<<gg, 256>>>(h2, W_l2, b_l2, out);

    (void)in_sizes; (void)n_in; (void)out_size;
}